// round 14
// baseline (speedup 1.0000x reference)
#include <cuda_runtime.h>
#include <cuda_fp16.h>
#include <cstdint>

// LoRALinear: out[8192,4096] = X[8192,4096] @ W_eff[4096,4096]^T + bias
//   W_eff = W + (alpha/r) * B @ A   (folded by prep_w_kernel)
// GEMM: mma.sync m16n8k16 f16 (f32 accum), ldmatrix loads, cp.async 3-stage.
// R14: 128x128 CTA tiles, 256 threads, 110.6KB smem -> 2 CTAs/SM so one CTA's
// prologue/epilogue overlaps the other's mainloop (tensor pipe never idles).
// Inputs (metadata order): x, weight, bias, A, B  -- all fp32.

#define IN_F   4096
#define OUT_F  4096
#define MDIM   8192
#define LORA_R 16
#define SCALING 2.0f   // 32.0 / 16

// ---- tiling ----
#define BM 128
#define BN 128
#define BK 64                  // fp16: 64 elems = 128B per row
#define STAGES 3
#define NIT (IN_F / BK)        // 64
#define ROWB 144               // 128B data + 16B pad -> conflict-free ldmatrix/cp.async
#define A_BYTES (BM * ROWB)    // 18432
#define B_BYTES (BN * ROWB)    // 18432
#define STG_BYTES (A_BYTES + B_BYTES)          // 36864
#define SMEM_TOTAL (STAGES * STG_BYTES)        // 110592  (x2 CTAs = 221184 <= 227KB)
#define NTHREADS 256

// ---- scratch (device globals: allocation-free rule) ----
__device__ __align__(128) __half g_Xh[(size_t)MDIM * IN_F];   // fp16 x
__device__ __align__(128) __half g_Wh[(size_t)OUT_F * IN_F];  // fp16 W_eff

// ============================ helpers ============================

__device__ __forceinline__ uint32_t smem_u32(const void* p) {
    uint32_t a;
    asm("{ .reg .u64 t; cvta.to.shared.u64 t, %1; cvt.u32.u64 %0, t; }" : "=r"(a) : "l"(p));
    return a;
}

__device__ __forceinline__ uint32_t h2_bits(__half2 h) {
    return *reinterpret_cast<uint32_t*>(&h);
}

__device__ __forceinline__ void cp_async16(uint32_t dst, const void* src) {
    asm volatile("cp.async.cg.shared.global [%0], [%1], 16;" :: "r"(dst), "l"(src));
}

__device__ __forceinline__ void mma_f16(float c[4], const uint32_t a[4],
                                        uint32_t b0, uint32_t b1) {
    asm volatile(
        "mma.sync.aligned.m16n8k16.row.col.f32.f16.f16.f32 "
        "{%0,%1,%2,%3}, {%4,%5,%6,%7}, {%8,%9}, {%0,%1,%2,%3};"
        : "+f"(c[0]), "+f"(c[1]), "+f"(c[2]), "+f"(c[3])
        : "r"(a[0]), "r"(a[1]), "r"(a[2]), "r"(a[3]), "r"(b0), "r"(b1));
}

#define LDSM_X4(r0, r1, r2, r3, addr) \
    asm volatile("ldmatrix.sync.aligned.m8n8.x4.shared.b16 {%0,%1,%2,%3}, [%4];" \
                 : "=r"(r0), "=r"(r1), "=r"(r2), "=r"(r3) : "r"(addr))

// ============================ prep kernels ============================

// x -> g_Xh (fp16, RN). Each thread: 8 floats -> 8 halves (one 16B store).
__global__ void prep_x_kernel(const float* __restrict__ x) {
    size_t i = (size_t)blockIdx.x * blockDim.x + threadIdx.x;
    const float4* p = reinterpret_cast<const float4*>(x) + i * 2;
    float4 v0 = p[0], v1 = p[1];
    uint4 o;
    o.x = h2_bits(__floats2half2_rn(v0.x, v0.y));
    o.y = h2_bits(__floats2half2_rn(v0.z, v0.w));
    o.z = h2_bits(__floats2half2_rn(v1.x, v1.y));
    o.w = h2_bits(__floats2half2_rn(v1.z, v1.w));
    reinterpret_cast<uint4*>(g_Xh)[i] = o;
}

// W_eff = fp16(W + SCALING * B @ A). Tile: 256 i-cols x 32 o-rows.
__global__ void prep_w_kernel(const float* __restrict__ weight,
                              const float* __restrict__ A,
                              const float* __restrict__ B) {
    __shared__ float As[LORA_R][256];
    __shared__ float Bs[32][LORA_R];
    int tid = threadIdx.x;
    int i0 = blockIdx.x * 256;
    int o0 = blockIdx.y * 32;

#pragma unroll
    for (int idx = tid; idx < LORA_R * 256; idx += 256)
        As[idx >> 8][idx & 255] = A[(idx >> 8) * IN_F + i0 + (idx & 255)];
    for (int idx = tid; idx < 32 * LORA_R; idx += 256)
        Bs[idx >> 4][idx & 15] = B[(size_t)(o0 + (idx >> 4)) * LORA_R + (idx & 15)];
    __syncthreads();

    int i = i0 + tid;
#pragma unroll 4
    for (int oo = 0; oo < 32; oo++) {
        float acc = 0.0f;
#pragma unroll
        for (int r = 0; r < LORA_R; r++) acc += Bs[oo][r] * As[r][tid];
        size_t idx = (size_t)(o0 + oo) * IN_F + i;
        g_Wh[idx] = __float2half_rn(weight[idx] + SCALING * acc);
    }
}

// ============================ GEMM ============================

// Load one K-stage: A tile 128x64 f16 (1024 16B chunks), B tile 128x64 (1024).
__device__ __forceinline__ void load_stage(uint32_t sbase, int stage,
                                           const __half* __restrict__ Xb,
                                           const __half* __restrict__ Wb,
                                           int kt, int tid) {
    uint32_t aB = sbase + stage * STG_BYTES;
    const __half* xs = Xb + kt * BK;
#pragma unroll
    for (int i = 0; i < 4; i++) {
        int c = tid + i * NTHREADS;
        int m = c >> 3, kc = c & 7;
        cp_async16(aB + m * ROWB + kc * 16, xs + (size_t)m * IN_F + kc * 8);
    }
    uint32_t bB = aB + A_BYTES;
    const __half* ws = Wb + kt * BK;
#pragma unroll
    for (int i = 0; i < 4; i++) {
        int c = tid + i * NTHREADS;
        int n = c >> 3, kc = c & 7;
        cp_async16(bB + n * ROWB + kc * 16, ws + (size_t)n * IN_F + kc * 8);
    }
}

__global__ void __launch_bounds__(NTHREADS, 2)
lora_gemm_kernel(const float* __restrict__ bias, float* __restrict__ out) {
    extern __shared__ __align__(128) char smem[];
    const uint32_t sbase = smem_u32(smem);
    const int tid = threadIdx.x;
    const int wid = tid >> 5, lane = tid & 31;
    const int g = lane >> 2, tg = lane & 3;     // groupID, threadID_in_group
    const int wm = wid & 1, wn = wid >> 1;      // 2x4 warp grid, 64x32 warp tiles

    const int nb = blockIdx.x & 31;             // 32 N-tiles (inner: share X band)
    const int mb = blockIdx.x >> 5;             // 64 M-tiles
    const int m0 = mb * BM, n0 = nb * BN;

    const __half* Xb = g_Xh + (size_t)m0 * IN_F;
    const __half* Wb = g_Wh + (size_t)n0 * IN_F;

    // Per-lane ldmatrix address pattern (identical formula for A and B tiles):
    //   quadrant q = lane>>3: row = (lane&7) + 8*(q&1), 16B-half = q>>1
    const uint32_t frag_off =
        (uint32_t)((lane & 7) + 8 * ((lane >> 3) & 1)) * ROWB + (uint32_t)(lane >> 4) * 16;
    const uint32_t a_off = (uint32_t)(wm * 64) * ROWB + frag_off;            // + mt*16*ROWB + ks*32
    const uint32_t b_off = A_BYTES + (uint32_t)(wn * 32) * ROWB + frag_off;  // + ntp*16*ROWB + ks*32

    float acc[4][4][4];
#pragma unroll
    for (int mt = 0; mt < 4; mt++)
#pragma unroll
        for (int nt = 0; nt < 4; nt++)
#pragma unroll
            for (int r = 0; r < 4; r++) acc[mt][nt][r] = 0.0f;

    // prologue
#pragma unroll
    for (int s = 0; s < STAGES - 1; s++) {
        load_stage(sbase, s, Xb, Wb, s, tid);
        asm volatile("cp.async.commit_group;" ::: "memory");
    }

    for (int kt = 0; kt < NIT; kt++) {
        const int s = kt % STAGES;
        asm volatile("cp.async.wait_group %0;" :: "n"(STAGES - 2) : "memory");
        __syncthreads();

        const int j = kt + STAGES - 1;
        if (j < NIT) load_stage(sbase, j % STAGES, Xb, Wb, j, tid);
        asm volatile("cp.async.commit_group;" ::: "memory");

        const uint32_t stA = sbase + s * STG_BYTES;
#pragma unroll
        for (int ks = 0; ks < 4; ks++) {       // 4 k-steps of k16 per BK=64 tile
            const uint32_t kadd = (uint32_t)(ks * 32);  // +16 halves in k
            uint32_t af[4][4], bf[2][4];
#pragma unroll
            for (int mt = 0; mt < 4; mt++)
                LDSM_X4(af[mt][0], af[mt][1], af[mt][2], af[mt][3],
                        stA + a_off + kadd + (uint32_t)(mt * 16 * ROWB));
#pragma unroll
            for (int ntp = 0; ntp < 2; ntp++)
                LDSM_X4(bf[ntp][0], bf[ntp][1], bf[ntp][2], bf[ntp][3],
                        stA + b_off + kadd + (uint32_t)(ntp * 16 * ROWB));
            // B x4 covers two nt tiles: nt even -> {r0,r2}, nt odd -> {r1,r3}
#pragma unroll
            for (int mt = 0; mt < 4; mt++)
#pragma unroll
                for (int nt = 0; nt < 4; nt++)
                    mma_f16(acc[mt][nt], af[mt],
                            bf[nt >> 1][nt & 1], bf[nt >> 1][(nt & 1) + 2]);
        }
    }

    // epilogue: bias add + float2 stores (cols 2tg,2tg+1 contiguous)
    const int ncol0 = n0 + wn * 32;
#pragma unroll
    for (int mt = 0; mt < 4; mt++) {
#pragma unroll
        for (int half = 0; half < 2; half++) {
            const int m = m0 + wm * 64 + mt * 16 + g + half * 8;
            float* orow = out + (size_t)m * OUT_F + ncol0;
#pragma unroll
            for (int nt = 0; nt < 4; nt++) {
                float2 bv = *reinterpret_cast<const float2*>(bias + ncol0 + nt * 8 + 2 * tg);
                float2 v;
                v.x = acc[mt][nt][half * 2 + 0] + bv.x;
                v.y = acc[mt][nt][half * 2 + 1] + bv.y;
                *reinterpret_cast<float2*>(orow + nt * 8 + 2 * tg) = v;
            }
        }
    }
}

// ============================ launch ============================

extern "C" void kernel_launch(void* const* d_in, const int* in_sizes, int n_in,
                              void* d_out, int out_size) {
    const float* x      = (const float*)d_in[0];  // [4,2048,4096]
    const float* weight = (const float*)d_in[1];  // [4096,4096]
    const float* bias   = (const float*)d_in[2];  // [4096]
    const float* A      = (const float*)d_in[3];  // [16,4096]
    const float* B      = (const float*)d_in[4];  // [4096,16]
    float* out = (float*)d_out;

    cudaFuncSetAttribute(lora_gemm_kernel, cudaFuncAttributeMaxDynamicSharedMemorySize,
                         SMEM_TOTAL);

    prep_x_kernel<<<(MDIM * IN_F / 8) / 256, 256>>>(x);            // 16384 blocks
    prep_w_kernel<<<dim3(IN_F / 256, OUT_F / 32), 256>>>(weight, A, B);
    lora_gemm_kernel<<<(MDIM / BM) * (OUT_F / BN), NTHREADS, SMEM_TOTAL>>>(bias, out);
}

// round 17
// speedup vs baseline: 1.6190x; 1.6190x over previous
#include <cuda_runtime.h>
#include <cuda_fp16.h>
#include <cstdint>

// LoRALinear: out[8192,4096] = X[8192,4096] @ W_eff[4096,4096]^T + bias
//   W_eff = W + (alpha/r) * B @ A   (folded by prep_w_kernel)
// GEMM: mma.sync m16n8k16 f16 (f32 accum), ldmatrix loads, cp.async 3-stage.
// R16 = R15 resubmit (R15 hit a broker infra failure: device busy before any
// launch). R13 champion shape (BM=256/BN=128, 512 thr, 16 warps) with the kt
// loop unrolled mod-3 so stage indices/addresses are compile-time constants.
// Inputs (metadata order): x, weight, bias, A, B  -- all fp32.

#define IN_F   4096
#define OUT_F  4096
#define MDIM   8192
#define LORA_R 16
#define SCALING 2.0f   // 32.0 / 16

// ---- tiling ----
#define BM 256
#define BN 128
#define BK 64                  // fp16: 64 elems = 128B per row
#define STAGES 3
#define NIT (IN_F / BK)        // 64
#define ROWB 144               // 128B data + 16B pad -> conflict-free ldmatrix/cp.async
#define A_BYTES (BM * ROWB)    // 36864
#define B_BYTES (BN * ROWB)    // 18432
#define STG_BYTES (A_BYTES + B_BYTES)          // 55296
#define SMEM_TOTAL (STAGES * STG_BYTES)        // 165888
#define NTHREADS 512

// ---- scratch (device globals: allocation-free rule) ----
__device__ __align__(128) __half g_Xh[(size_t)MDIM * IN_F];   // fp16 x
__device__ __align__(128) __half g_Wh[(size_t)OUT_F * IN_F];  // fp16 W_eff

// ============================ helpers ============================

__device__ __forceinline__ uint32_t smem_u32(const void* p) {
    uint32_t a;
    asm("{ .reg .u64 t; cvta.to.shared.u64 t, %1; cvt.u32.u64 %0, t; }" : "=r"(a) : "l"(p));
    return a;
}

__device__ __forceinline__ uint32_t h2_bits(__half2 h) {
    return *reinterpret_cast<uint32_t*>(&h);
}

__device__ __forceinline__ void cp_async16(uint32_t dst, const void* src) {
    asm volatile("cp.async.cg.shared.global [%0], [%1], 16;" :: "r"(dst), "l"(src));
}

__device__ __forceinline__ void mma_f16(float c[4], const uint32_t a[4],
                                        uint32_t b0, uint32_t b1) {
    asm volatile(
        "mma.sync.aligned.m16n8k16.row.col.f32.f16.f16.f32 "
        "{%0,%1,%2,%3}, {%4,%5,%6,%7}, {%8,%9}, {%0,%1,%2,%3};"
        : "+f"(c[0]), "+f"(c[1]), "+f"(c[2]), "+f"(c[3])
        : "r"(a[0]), "r"(a[1]), "r"(a[2]), "r"(a[3]), "r"(b0), "r"(b1));
}

#define LDSM_X4(r0, r1, r2, r3, addr) \
    asm volatile("ldmatrix.sync.aligned.m8n8.x4.shared.b16 {%0,%1,%2,%3}, [%4];" \
                 : "=r"(r0), "=r"(r1), "=r"(r2), "=r"(r3) : "r"(addr))

// ============================ prep kernels ============================

// x -> g_Xh (fp16, RN). Each thread: 8 floats -> 8 halves (one 16B store).
__global__ void prep_x_kernel(const float* __restrict__ x) {
    size_t i = (size_t)blockIdx.x * blockDim.x + threadIdx.x;
    const float4* p = reinterpret_cast<const float4*>(x) + i * 2;
    float4 v0 = p[0], v1 = p[1];
    uint4 o;
    o.x = h2_bits(__floats2half2_rn(v0.x, v0.y));
    o.y = h2_bits(__floats2half2_rn(v0.z, v0.w));
    o.z = h2_bits(__floats2half2_rn(v1.x, v1.y));
    o.w = h2_bits(__floats2half2_rn(v1.z, v1.w));
    reinterpret_cast<uint4*>(g_Xh)[i] = o;
}

// W_eff = fp16(W + SCALING * B @ A). Tile: 256 i-cols x 32 o-rows.
__global__ void prep_w_kernel(const float* __restrict__ weight,
                              const float* __restrict__ A,
                              const float* __restrict__ B) {
    __shared__ float As[LORA_R][256];
    __shared__ float Bs[32][LORA_R];
    int tid = threadIdx.x;
    int i0 = blockIdx.x * 256;
    int o0 = blockIdx.y * 32;

#pragma unroll
    for (int idx = tid; idx < LORA_R * 256; idx += 256)
        As[idx >> 8][idx & 255] = A[(idx >> 8) * IN_F + i0 + (idx & 255)];
    for (int idx = tid; idx < 32 * LORA_R; idx += 256)
        Bs[idx >> 4][idx & 15] = B[(size_t)(o0 + (idx >> 4)) * LORA_R + (idx & 15)];
    __syncthreads();

    int i = i0 + tid;
#pragma unroll 4
    for (int oo = 0; oo < 32; oo++) {
        float acc = 0.0f;
#pragma unroll
        for (int r = 0; r < LORA_R; r++) acc += Bs[oo][r] * As[r][tid];
        size_t idx = (size_t)(o0 + oo) * IN_F + i;
        g_Wh[idx] = __float2half_rn(weight[idx] + SCALING * acc);
    }
}

// ============================ GEMM ============================

// Load one K-stage: A tile 256x64 f16 (2048 16B chunks), B tile 128x64 (1024).
__device__ __forceinline__ void load_stage(uint32_t sbase, int stage,
                                           const __half* __restrict__ Xb,
                                           const __half* __restrict__ Wb,
                                           int kt, int tid) {
    uint32_t aB = sbase + stage * STG_BYTES;
    const __half* xs = Xb + kt * BK;
#pragma unroll
    for (int i = 0; i < 4; i++) {
        int c = tid + i * NTHREADS;
        int m = c >> 3, kc = c & 7;
        cp_async16(aB + m * ROWB + kc * 16, xs + (size_t)m * IN_F + kc * 8);
    }
    uint32_t bB = aB + A_BYTES;
    const __half* ws = Wb + kt * BK;
#pragma unroll
    for (int i = 0; i < 2; i++) {
        int c = tid + i * NTHREADS;
        int n = c >> 3, kc = c & 7;
        cp_async16(bB + n * ROWB + kc * 16, ws + (size_t)n * IN_F + kc * 8);
    }
}

// Compute all 4 k-steps of one resident stage (stage base passed as constant).
__device__ __forceinline__ void compute_stage(uint32_t stA, uint32_t a_off, uint32_t b_off,
                                              float acc[4][4][4]) {
#pragma unroll
    for (int ks = 0; ks < 4; ks++) {           // 4 k-steps of k16 per BK=64 tile
        const uint32_t kadd = (uint32_t)(ks * 32);  // +16 halves in k
        uint32_t af[4][4], bf[2][4];
#pragma unroll
        for (int mt = 0; mt < 4; mt++)
            LDSM_X4(af[mt][0], af[mt][1], af[mt][2], af[mt][3],
                    stA + a_off + kadd + (uint32_t)(mt * 16 * ROWB));
#pragma unroll
        for (int ntp = 0; ntp < 2; ntp++)
            LDSM_X4(bf[ntp][0], bf[ntp][1], bf[ntp][2], bf[ntp][3],
                    stA + b_off + kadd + (uint32_t)(ntp * 16 * ROWB));
        // B x4 covers two nt tiles: nt even -> {r0,r2}, nt odd -> {r1,r3}
#pragma unroll
        for (int mt = 0; mt < 4; mt++)
#pragma unroll
            for (int nt = 0; nt < 4; nt++)
                mma_f16(acc[mt][nt], af[mt],
                        bf[nt >> 1][nt & 1], bf[nt >> 1][(nt & 1) + 2]);
    }
}

__global__ void __launch_bounds__(NTHREADS, 1)
lora_gemm_kernel(const float* __restrict__ bias, float* __restrict__ out) {
    extern __shared__ __align__(128) char smem[];
    const uint32_t sbase = smem_u32(smem);
    const int tid = threadIdx.x;
    const int wid = tid >> 5, lane = tid & 31;
    const int g = lane >> 2, tg = lane & 3;     // groupID, threadID_in_group
    const int wm = wid & 3, wn = wid >> 2;      // 4x4 warp grid, 64x32 warp tiles

    const int nb = blockIdx.x & 31;             // 32 N-tiles (inner: share X band)
    const int mb = blockIdx.x >> 5;             // 32 M-tiles
    const int m0 = mb * BM, n0 = nb * BN;

    const __half* Xb = g_Xh + (size_t)m0 * IN_F;
    const __half* Wb = g_Wh + (size_t)n0 * IN_F;

    // Per-lane ldmatrix address pattern (identical formula for A and B tiles):
    //   quadrant q = lane>>3: row = (lane&7) + 8*(q&1), 16B-half = q>>1
    const uint32_t frag_off =
        (uint32_t)((lane & 7) + 8 * ((lane >> 3) & 1)) * ROWB + (uint32_t)(lane >> 4) * 16;
    const uint32_t a_off = (uint32_t)(wm * 64) * ROWB + frag_off;            // + mt*16*ROWB + ks*32
    const uint32_t b_off = A_BYTES + (uint32_t)(wn * 32) * ROWB + frag_off;  // + ntp*16*ROWB + ks*32

    float acc[4][4][4];
#pragma unroll
    for (int mt = 0; mt < 4; mt++)
#pragma unroll
        for (int nt = 0; nt < 4; nt++)
#pragma unroll
            for (int r = 0; r < 4; r++) acc[mt][nt][r] = 0.0f;

    // prologue: fill stages 0,1
#pragma unroll
    for (int s = 0; s < STAGES - 1; s++) {
        load_stage(sbase, s, Xb, Wb, s, tid);
        asm volatile("cp.async.commit_group;" ::: "memory");
    }

    // one pipeline step with compile-time stage S for iteration KT
#define KT_STEP(KT, S) do {                                                    \
        asm volatile("cp.async.wait_group 1;" ::: "memory");                   \
        __syncthreads();                                                       \
        if ((KT) + (STAGES - 1) < NIT)                                         \
            load_stage(sbase, ((S) + STAGES - 1) % STAGES, Xb, Wb,             \
                       (KT) + (STAGES - 1), tid);                              \
        asm volatile("cp.async.commit_group;" ::: "memory");                   \
        compute_stage(sbase + (S) * STG_BYTES, a_off, b_off, acc);             \
    } while (0)

    // NIT = 64 = 21*3 + 1: unroll mod-3 so stage indices are constants
#pragma unroll 1
    for (int base = 0; base < 63; base += 3) {
        KT_STEP(base + 0, 0);
        KT_STEP(base + 1, 1);
        KT_STEP(base + 2, 2);
    }
    KT_STEP(63, 0);
#undef KT_STEP

    // epilogue: bias add + float2 stores (cols 2tg,2tg+1 contiguous)
    const int ncol0 = n0 + wn * 32;
#pragma unroll
    for (int mt = 0; mt < 4; mt++) {
#pragma unroll
        for (int half = 0; half < 2; half++) {
            const int m = m0 + wm * 64 + mt * 16 + g + half * 8;
            float* orow = out + (size_t)m * OUT_F + ncol0;
#pragma unroll
            for (int nt = 0; nt < 4; nt++) {
                float2 bv = *reinterpret_cast<const float2*>(bias + ncol0 + nt * 8 + 2 * tg);
                float2 v;
                v.x = acc[mt][nt][half * 2 + 0] + bv.x;
                v.y = acc[mt][nt][half * 2 + 1] + bv.y;
                *reinterpret_cast<float2*>(orow + nt * 8 + 2 * tg) = v;
            }
        }
    }
}

// ============================ launch ============================

extern "C" void kernel_launch(void* const* d_in, const int* in_sizes, int n_in,
                              void* d_out, int out_size) {
    const float* x      = (const float*)d_in[0];  // [4,2048,4096]
    const float* weight = (const float*)d_in[1];  // [4096,4096]
    const float* bias   = (const float*)d_in[2];  // [4096]
    const float* A      = (const float*)d_in[3];  // [16,4096]
    const float* B      = (const float*)d_in[4];  // [4096,16]
    float* out = (float*)d_out;

    cudaFuncSetAttribute(lora_gemm_kernel, cudaFuncAttributeMaxDynamicSharedMemorySize,
                         SMEM_TOTAL);

    prep_x_kernel<<<(MDIM * IN_F / 8) / 256, 256>>>(x);            // 16384 blocks
    prep_w_kernel<<<dim3(IN_F / 256, OUT_F / 32), 256>>>(weight, A, B);
    lora_gemm_kernel<<<(MDIM / BM) * (OUT_F / BN), NTHREADS, SMEM_TOTAL>>>(bias, out);
}